// round 1
// baseline (speedup 1.0000x reference)
#include <cuda_runtime.h>
#include <cfloat>

// Problem constants (from reference: B=2048, N=100000, D=512, fp32)
#define Bq 2048
#define Nn 100000
#define Dd 512

// Main-kernel tiling
#define TM 128          // queries per block tile
#define TN 128          // buffer rows per block tile
#define BK 8            // k-slice
#define NSPLIT 37       // splits of N across blockIdx.y
#define ROWS_PER_SPLIT ((Nn + NSPLIT - 1) / NSPLIT)   // 2703

// Scratch (no cudaMalloc allowed): device globals.
__device__ float g_b2[Nn];
__device__ float g_pv[NSPLIT * Bq];
__device__ int   g_pi[NSPLIT * Bq];

// ---------------------------------------------------------------------------
// Kernel 1: b2[n] = ||buffer[n]||^2.  One warp per row, float4 loads.
// ---------------------------------------------------------------------------
__global__ void knn_b2_kernel(const float* __restrict__ buf) {
    int warp = threadIdx.x >> 5;
    int lane = threadIdx.x & 31;
    int row  = blockIdx.x * 8 + warp;
    if (row >= Nn) return;
    const float4* p = reinterpret_cast<const float4*>(buf + (size_t)row * Dd);
    float s = 0.f;
#pragma unroll
    for (int c = lane; c < Dd / 4; c += 32) {
        float4 v = p[c];
        s += v.x * v.x + v.y * v.y + v.z * v.z + v.w * v.w;
    }
#pragma unroll
    for (int o = 16; o > 0; o >>= 1) s += __shfl_down_sync(0xffffffffu, s, o);
    if (lane == 0) g_b2[row] = s;
}

// ---------------------------------------------------------------------------
// Kernel 2: fused GEMM + streaming argmin.
// Block (x = query tile, y = N split). 256 threads, 8x8 register tile each.
// Computes dot(q, b) for a 128x128 tile per chunk, folds d2 = b2 - 2*dot into
// per-query running (min, idx), writes per-split partials.
// ---------------------------------------------------------------------------
__global__ __launch_bounds__(256, 2) void knn_main_kernel(
    const float* __restrict__ Q, const float* __restrict__ Bf) {
    __shared__ float sQ[BK][TM];   // k-major so LDS.128 grabs 4 queries per k
    __shared__ float sB[BK][TN];
    __shared__ float rv[16][TM];
    __shared__ int   ri[16][TM];

    const int q0      = blockIdx.x * TM;
    const int split   = blockIdx.y;
    const int n_begin = split * ROWS_PER_SPLIT;
    const int n_end   = min(Nn, n_begin + ROWS_PER_SPLIT);

    const int tid = threadIdx.x;
    const int tx  = tid & 15;    // buffer-row group (8 rows)
    const int ty  = tid >> 4;    // query group (8 queries)

    // global->smem load mapping: each thread loads one float4 per tile side
    const int lrow = tid >> 1;          // 0..127
    const int lk4  = (tid & 1) * 4;     // 0 or 4

    float minv[8];
    int   mini[8];
#pragma unroll
    for (int i = 0; i < 8; i++) { minv[i] = FLT_MAX; mini[i] = 0; }

    for (int n0 = n_begin; n0 < n_end; n0 += TN) {
        float acc[8][8];
#pragma unroll
        for (int i = 0; i < 8; i++)
#pragma unroll
            for (int j = 0; j < 8; j++) acc[i][j] = 0.f;

        for (int k0 = 0; k0 < Dd; k0 += BK) {
            // issue global loads before the barrier
            float4 qv = *reinterpret_cast<const float4*>(
                Q + (size_t)(q0 + lrow) * Dd + k0 + lk4);
            float4 bv = make_float4(0.f, 0.f, 0.f, 0.f);
            int brow = n0 + lrow;
            if (brow < n_end)
                bv = *reinterpret_cast<const float4*>(
                    Bf + (size_t)brow * Dd + k0 + lk4);

            __syncthreads();   // previous compute done before overwrite
            sQ[lk4 + 0][lrow] = qv.x;
            sQ[lk4 + 1][lrow] = qv.y;
            sQ[lk4 + 2][lrow] = qv.z;
            sQ[lk4 + 3][lrow] = qv.w;
            sB[lk4 + 0][lrow] = bv.x;
            sB[lk4 + 1][lrow] = bv.y;
            sB[lk4 + 2][lrow] = bv.z;
            sB[lk4 + 3][lrow] = bv.w;
            __syncthreads();

#pragma unroll
            for (int kk = 0; kk < BK; kk++) {
                float4 a0 = *reinterpret_cast<const float4*>(&sQ[kk][ty * 8]);
                float4 a1 = *reinterpret_cast<const float4*>(&sQ[kk][ty * 8 + 4]);
                float4 b0 = *reinterpret_cast<const float4*>(&sB[kk][tx * 8]);
                float4 b1 = *reinterpret_cast<const float4*>(&sB[kk][tx * 8 + 4]);
                float a[8] = {a0.x, a0.y, a0.z, a0.w, a1.x, a1.y, a1.z, a1.w};
                float b[8] = {b0.x, b0.y, b0.z, b0.w, b1.x, b1.y, b1.z, b1.w};
#pragma unroll
                for (int i = 0; i < 8; i++)
#pragma unroll
                    for (int j = 0; j < 8; j++)
                        acc[i][j] = fmaf(a[i], b[j], acc[i][j]);
            }
        }

        // fold chunk into running (min, argmin).  d2 = b2 - 2*dot  (q2 const)
#pragma unroll
        for (int j = 0; j < 8; j++) {
            int n = n0 + tx * 8 + j;
            float bb2 = (n < n_end) ? g_b2[n] : FLT_MAX;
#pragma unroll
            for (int i = 0; i < 8; i++) {
                float d = fmaf(-2.f, acc[i][j], bb2);
                if (d < minv[i]) { minv[i] = d; mini[i] = n; }
            }
        }
    }

    // cross-thread (tx) reduction per query
#pragma unroll
    for (int i = 0; i < 8; i++) {
        rv[tx][ty * 8 + i] = minv[i];
        ri[tx][ty * 8 + i] = mini[i];
    }
    __syncthreads();
    if (tid < TM) {
        float v = rv[0][tid];
        int idx = ri[0][tid];
#pragma unroll
        for (int t = 1; t < 16; t++) {
            float vv = rv[t][tid];        // idx ascending with t: strict <
            if (vv < v) { v = vv; idx = ri[t][tid]; }
        }
        g_pv[split * Bq + q0 + tid] = v;
        g_pi[split * Bq + q0 + tid] = idx;
    }
}

// ---------------------------------------------------------------------------
// Kernel 3: reduce over splits + gather winning buffer row to output.
// One block per query, 128 threads (512 floats = 128 float4).
// ---------------------------------------------------------------------------
__global__ void knn_reduce_kernel(const float* __restrict__ Bf,
                                  float* __restrict__ out) {
    int q = blockIdx.x;
    __shared__ int s_idx;
    if (threadIdx.x == 0) {
        float v = g_pv[q];
        int idx = g_pi[q];
#pragma unroll 1
        for (int s = 1; s < NSPLIT; s++) {   // split index ascending: strict <
            float vv = g_pv[s * Bq + q];
            if (vv < v) { v = vv; idx = g_pi[s * Bq + q]; }
        }
        s_idx = idx;
    }
    __syncthreads();
    int idx = s_idx;
    const float4* src = reinterpret_cast<const float4*>(Bf + (size_t)idx * Dd);
    float4* dst = reinterpret_cast<float4*>(out + (size_t)q * Dd);
    dst[threadIdx.x] = src[threadIdx.x];
}

// ---------------------------------------------------------------------------
extern "C" void kernel_launch(void* const* d_in, const int* in_sizes, int n_in,
                              void* d_out, int out_size) {
    const float* Q  = (const float*)d_in[0];   // inputs  [2048, 512]
    const float* Bf = (const float*)d_in[1];   // buffer  [100000, 512]
    float* out = (float*)d_out;                // [2048, 512]

    knn_b2_kernel<<<(Nn + 7) / 8, 256>>>(Bf);
    dim3 grid(Bq / TM, NSPLIT);
    knn_main_kernel<<<grid, 256>>>(Q, Bf);
    knn_reduce_kernel<<<Bq, 128>>>(Bf, out);
}

// round 3
// speedup vs baseline: 7.4159x; 7.4159x over previous
#include <cuda_runtime.h>
#include <cuda_bf16.h>
#include <cfloat>
#include <cstdint>

#define Bq 2048
#define Nn 100000
#define Dd 512
#define BM 128
#define BN 128
#define NSPLIT 37
#define RPS 2703                 // ceil(Nn / NSPLIT)
#define NCAND (2 * NSPLIT)
#define MARGIN 2.0f

// ---- device-global scratch (no allocs allowed) ----
__device__ __nv_bfloat16 g_qbf[Bq * Dd];                 // 2 MB
__device__ __nv_bfloat16 g_bbuf[(Nn + 160) * Dd];        // ~102.5 MB (pad rows stay 0)
__device__ float g_b2[Nn];
__device__ float g_pv[NCAND * Bq];
__device__ int   g_pi[NCAND * Bq];

// ---------------------------------------------------------------------------
// helpers
// ---------------------------------------------------------------------------
// 64B-row tile; 16B-granule swizzle keeps 8-row ldmatrix conflict-free:
// granule position (4r + c16')%8 distinct for r=0..7 with c16' = c16 ^ ((r>>1)&3)
__device__ __forceinline__ uint32_t swz(uint32_t row, uint32_t c16) {
    return row * 64u + ((c16 ^ ((row >> 1) & 3u)) << 4);
}
__device__ __forceinline__ void cpasync16(uint32_t dst, const void* src) {
    asm volatile("cp.async.cg.shared.global [%0], [%1], 16;" :: "r"(dst), "l"(src));
}
__device__ __forceinline__ void cp_commit() { asm volatile("cp.async.commit_group;"); }
__device__ __forceinline__ void cp_wait1()  { asm volatile("cp.async.wait_group 1;"); }
__device__ __forceinline__ void ldsm4(uint32_t& r0, uint32_t& r1, uint32_t& r2, uint32_t& r3,
                                      uint32_t a) {
    asm volatile("ldmatrix.sync.aligned.m8n8.x4.shared.b16 {%0,%1,%2,%3}, [%4];"
                 : "=r"(r0), "=r"(r1), "=r"(r2), "=r"(r3) : "r"(a));
}
__device__ __forceinline__ void mma16816(float c[4], uint32_t a0, uint32_t a1, uint32_t a2,
                                         uint32_t a3, uint32_t b0, uint32_t b1) {
    asm volatile(
        "mma.sync.aligned.m16n8k16.row.col.f32.bf16.bf16.f32 "
        "{%0,%1,%2,%3},{%4,%5,%6,%7},{%8,%9},{%0,%1,%2,%3};"
        : "+f"(c[0]), "+f"(c[1]), "+f"(c[2]), "+f"(c[3])
        : "r"(a0), "r"(a1), "r"(a2), "r"(a3), "r"(b0), "r"(b1));
}

// ---------------------------------------------------------------------------
// Kernel: convert Q fp32 -> bf16
// ---------------------------------------------------------------------------
__global__ void knn_convq_kernel(const float* __restrict__ Q) {
    int i = blockIdx.x * 256 + threadIdx.x;      // float4 index; total Bq*Dd/4
    float4 v = reinterpret_cast<const float4*>(Q)[i];
    __nv_bfloat162* dst = reinterpret_cast<__nv_bfloat162*>(g_qbf);
    dst[2 * i]     = __floats2bfloat162_rn(v.x, v.y);
    dst[2 * i + 1] = __floats2bfloat162_rn(v.z, v.w);
}

// ---------------------------------------------------------------------------
// Kernel: convert buffer fp32 -> bf16 and compute b2 (fp32). Warp per row.
// ---------------------------------------------------------------------------
__global__ void knn_convb_kernel(const float* __restrict__ Bf) {
    int warp = threadIdx.x >> 5, lane = threadIdx.x & 31;
    int row = blockIdx.x * 8 + warp;
    if (row >= Nn) return;
    const float4* src = reinterpret_cast<const float4*>(Bf + (size_t)row * Dd);
    __nv_bfloat162* dst = reinterpret_cast<__nv_bfloat162*>(g_bbuf + (size_t)row * Dd);
    float s = 0.f;
#pragma unroll
    for (int it = 0; it < 4; it++) {
        int c = lane + 32 * it;
        float4 v = src[c];
        s += v.x * v.x + v.y * v.y + v.z * v.z + v.w * v.w;
        dst[2 * c]     = __floats2bfloat162_rn(v.x, v.y);
        dst[2 * c + 1] = __floats2bfloat162_rn(v.z, v.w);
    }
#pragma unroll
    for (int o = 16; o > 0; o >>= 1) s += __shfl_down_sync(0xffffffffu, s, o);
    if (lane == 0) g_b2[row] = s;
}

// ---------------------------------------------------------------------------
// Main kernel: bf16 MMA GEMM + per-(query,split) top-2 of approx d2.
// grid = (16 query tiles, 37 splits), 256 threads, 8 warps (4 m x 2 n),
// warp tile 32(m) x 64(n), K chunked 32 with 3-stage cp.async pipeline.
// ---------------------------------------------------------------------------
__global__ __launch_bounds__(256) void knn_mma_kernel() {
    __shared__ __align__(1024) unsigned char smem_raw[3 * 16384];  // 48 KB exactly
    const int tid    = threadIdx.x;
    const int lane   = tid & 31;
    const int wid    = tid >> 5;
    const int warp_m = wid >> 1;
    const int warp_n = wid & 1;
    const int q0     = blockIdx.x * BM;
    const int split  = blockIdx.y;
    const int n_begin = split * RPS;
    const int n_end   = min(Nn, n_begin + RPS);

    const uint32_t smem_base = (uint32_t)__cvta_generic_to_shared(smem_raw);

    // per-thread top-2 for its 4 query rows
    float v1[4], v2[4];
    int   i1[4], i2[4];
#pragma unroll
    for (int r = 0; r < 4; r++) { v1[r] = FLT_MAX; v2[r] = FLT_MAX; i1[r] = -1; i2[r] = -1; }

    // ldmatrix lane address components
    const uint32_t qq = lane >> 3, l7 = lane & 7;
    const uint32_t a_row = (qq & 1) * 8 + l7;   // A x4: m0(r0-7,k0-7) m1(r8-15,k0-7) m2(r0-7,k8-15) m3
    const uint32_t a_c   = qq >> 1;
    const uint32_t b_row = (qq >> 1) * 8 + l7;  // B x4: (n0-7,k0-7)(n0-7,k8-15)(n8-15,k0-7)(n8-15,k8-15)
    const uint32_t b_c   = qq & 1;

    for (int n0 = n_begin; n0 < n_end; n0 += BN) {
        __syncthreads();   // protect smem stages & epilogue from previous chunk

        float acc[2][8][4];
#pragma unroll
        for (int mt = 0; mt < 2; mt++)
#pragma unroll
            for (int nt = 0; nt < 8; nt++)
#pragma unroll
                for (int e = 0; e < 4; e++) acc[mt][nt][e] = 0.f;

        auto prefetch = [&](int kc, int st) {
            uint32_t qb = smem_base + st * 16384;
            uint32_t bb = qb + 8192;
#pragma unroll
            for (int t2 = 0; t2 < 2; t2++) {
                int linr = tid + 256 * t2;
                int row  = linr >> 2;
                int c16  = linr & 3;
                const __nv_bfloat16* qs = g_qbf + (size_t)(q0 + row) * Dd + kc * 32 + c16 * 8;
                const __nv_bfloat16* bs = g_bbuf + (size_t)(n0 + row) * Dd + kc * 32 + c16 * 8;
                cpasync16(qb + swz(row, c16), qs);
                cpasync16(bb + swz(row, c16), bs);
            }
            cp_commit();
        };

        prefetch(0, 0);
        prefetch(1, 1);

#pragma unroll 1
        for (int kc = 0; kc < 16; kc++) {
            cp_wait1();          // stage kc complete (this thread's part)
            __syncthreads();     // all threads' parts visible; prev compute done
            if (kc + 2 < 16) prefetch(kc + 2, (kc + 2) % 3);
            else             cp_commit();   // empty group keeps wait_group math uniform

            const int st = kc % 3;
            const uint32_t qb = smem_base + st * 16384;
            const uint32_t bb = qb + 8192;
#pragma unroll
            for (int ks = 0; ks < 2; ks++) {
                uint32_t a[2][4];
#pragma unroll
                for (int mt = 0; mt < 2; mt++)
                    ldsm4(a[mt][0], a[mt][1], a[mt][2], a[mt][3],
                          qb + swz(warp_m * 32 + mt * 16 + a_row, 2 * ks + a_c));
                uint32_t b[8][2];
#pragma unroll
                for (int ntp = 0; ntp < 4; ntp++) {
                    uint32_t r0, r1, r2, r3;
                    ldsm4(r0, r1, r2, r3,
                          bb + swz(warp_n * 64 + ntp * 16 + b_row, 2 * ks + b_c));
                    b[2 * ntp][0] = r0; b[2 * ntp][1] = r1;
                    b[2 * ntp + 1][0] = r2; b[2 * ntp + 1][1] = r3;
                }
#pragma unroll
                for (int mt = 0; mt < 2; mt++)
#pragma unroll
                    for (int nt = 0; nt < 8; nt++)
                        mma16816(acc[mt][nt], a[mt][0], a[mt][1], a[mt][2], a[mt][3],
                                 b[nt][0], b[nt][1]);
            }
        }

        // fold chunk into per-row top-2:  d2 = b2[n] - 2*dot  (q2 constant per query)
        const int cbase = n0 + warp_n * 64 + 2 * (lane & 3);
#pragma unroll
        for (int nt = 0; nt < 8; nt++) {
#pragma unroll
            for (int e = 0; e < 2; e++) {
                int n = cbase + nt * 8 + e;
                float b2v = (n < Nn) ? g_b2[n] : FLT_MAX;
#pragma unroll
                for (int mt = 0; mt < 2; mt++)
#pragma unroll
                    for (int h = 0; h < 2; h++) {
                        int rr = mt * 2 + h;
                        float d = fmaf(-2.f, acc[mt][nt][h * 2 + e], b2v);
                        if (d < v2[rr]) {
                            if (d < v1[rr]) {
                                v2[rr] = v1[rr]; i2[rr] = i1[rr];
                                v1[rr] = d;      i1[rr] = n;
                            } else { v2[rr] = d; i2[rr] = n; }
                        }
                    }
            }
        }
    }

    // merge top-2 across the 4 lanes of each quad (same rows)
#pragma unroll
    for (int m = 1; m < 4; m <<= 1) {
#pragma unroll
        for (int rr = 0; rr < 4; rr++) {
            float w1 = __shfl_xor_sync(0xffffffffu, v1[rr], m);
            int   j1 = __shfl_xor_sync(0xffffffffu, i1[rr], m);
            float w2 = __shfl_xor_sync(0xffffffffu, v2[rr], m);
            int   j2 = __shfl_xor_sync(0xffffffffu, i2[rr], m);
            if (w1 < v1[rr]) { float t = v1[rr]; int ti = i1[rr];
                               v1[rr] = w1; i1[rr] = j1; w1 = t; j1 = ti; }
            float s = v2[rr]; int si = i2[rr];
            if (w2 < s) { s = w2; si = j2; }
            if (w1 < s) { s = w1; si = j1; }
            v2[rr] = s; i2[rr] = si;
        }
    }

    __syncthreads();   // safe to reuse tile smem for the reduction
    float* rv = reinterpret_cast<float*>(smem_raw);          // 512 floats
    int*   ri = reinterpret_cast<int*>(smem_raw + 2048);     // 512 ints
    if ((lane & 3) == 0) {
#pragma unroll
        for (int rr = 0; rr < 4; rr++) {
            int mt = rr >> 1, h = rr & 1;
            int row = warp_m * 32 + mt * 16 + h * 8 + (lane >> 2);
            rv[(warp_n * 2 + 0) * BM + row] = v1[rr];
            rv[(warp_n * 2 + 1) * BM + row] = v2[rr];
            ri[(warp_n * 2 + 0) * BM + row] = i1[rr];
            ri[(warp_n * 2 + 1) * BM + row] = i2[rr];
        }
    }
    __syncthreads();
    if (tid < BM) {
        float a1 = rv[0 * BM + tid], a2 = rv[1 * BM + tid];
        int   x1 = ri[0 * BM + tid], x2 = ri[1 * BM + tid];
        float w1 = rv[2 * BM + tid], w2 = rv[3 * BM + tid];
        int   y1 = ri[2 * BM + tid], y2 = ri[3 * BM + tid];
        if (w1 < a1) { float t = a1; int ti = x1; a1 = w1; x1 = y1; w1 = t; y1 = ti; }
        float s = a2; int si = x2;
        if (w2 < s) { s = w2; si = y2; }
        if (w1 < s) { s = w1; si = y1; }
        g_pv[(2 * split) * Bq + q0 + tid]     = a1;
        g_pi[(2 * split) * Bq + q0 + tid]     = x1;
        g_pv[(2 * split + 1) * Bq + q0 + tid] = s;
        g_pi[(2 * split + 1) * Bq + q0 + tid] = si;
    }
}

// ---------------------------------------------------------------------------
// Rescore: per query, exact fp32 d2 for candidates within MARGIN of approx min,
// then gather winning row. Block per query, 128 threads.
// ---------------------------------------------------------------------------
__global__ void knn_rescore_kernel(const float* __restrict__ Q, const float* __restrict__ Bf,
                                   float* __restrict__ out) {
    const int q = blockIdx.x;
    const int tid = threadIdx.x;
    const int lane = tid & 31;
    const int w = tid >> 5;
    __shared__ float s_v[NCAND];
    __shared__ int   s_i[NCAND];
    __shared__ float s_min, s_best, s_part[4];
    __shared__ int   s_bidx;
    if (tid < NCAND) { s_v[tid] = g_pv[tid * Bq + q]; s_i[tid] = g_pi[tid * Bq + q]; }
    if (tid == 0) { s_best = FLT_MAX; s_bidx = 0x7fffffff; }
    __syncthreads();
    if (tid == 0) {
        float m = FLT_MAX;
        for (int c = 0; c < NCAND; c++) m = fminf(m, s_v[c]);
        s_min = m;
    }
    __syncthreads();
    float4 q4 = reinterpret_cast<const float4*>(Q + (size_t)q * Dd)[tid];
    for (int c = 0; c < NCAND; c++) {
        float vc = s_v[c]; int ic = s_i[c];
        if (ic >= 0 && vc <= s_min + MARGIN) {        // uniform across block
            float4 b4 = reinterpret_cast<const float4*>(Bf + (size_t)ic * Dd)[tid];
            float p = q4.x * b4.x + q4.y * b4.y + q4.z * b4.z + q4.w * b4.w;
#pragma unroll
            for (int o = 16; o > 0; o >>= 1) p += __shfl_down_sync(0xffffffffu, p, o);
            if (lane == 0) s_part[w] = p;
            __syncthreads();
            if (tid == 0) {
                float dot = s_part[0] + s_part[1] + s_part[2] + s_part[3];
                float d = g_b2[ic] - 2.f * dot;
                if (d < s_best || (d == s_best && ic < s_bidx)) { s_best = d; s_bidx = ic; }
            }
            __syncthreads();
        }
    }
    __syncthreads();
    int bi = s_bidx;
    reinterpret_cast<float4*>(out + (size_t)q * Dd)[tid] =
        reinterpret_cast<const float4*>(Bf + (size_t)bi * Dd)[tid];
}

// ---------------------------------------------------------------------------
extern "C" void kernel_launch(void* const* d_in, const int* in_sizes, int n_in,
                              void* d_out, int out_size) {
    const float* Q  = (const float*)d_in[0];   // [2048, 512]
    const float* Bf = (const float*)d_in[1];   // [100000, 512]
    float* out = (float*)d_out;                // [2048, 512]

    knn_convq_kernel<<<(Bq * Dd / 4) / 256, 256>>>(Q);
    knn_convb_kernel<<<(Nn + 7) / 8, 256>>>(Bf);
    dim3 grid(Bq / BM, NSPLIT);
    knn_mma_kernel<<<grid, 256>>>();
    knn_rescore_kernel<<<Bq, 128>>>(Q, Bf, out);
}